// round 1
// baseline (speedup 1.0000x reference)
#include <cuda_runtime.h>
#include <math.h>

#define TT 2048
#define BB 8
#define FF 768
#define HH 3
#define DD 256
#define MM (TT*BB)      // 16384
#define BHN (BB*HH)     // 24

// Scratch (static device globals — allocation-free rule)
__device__ __align__(16) float g_q[BHN * TT * DD];               // (B*H, T, D)
__device__ __align__(16) float g_k[BHN * TT * DD];
__device__ __align__(16) float g_v[BHN * TT * DD];
__device__ __align__(16) float g_s[(size_t)BHN * TT * TT];       // (B*H, T, T)  402 MB
__device__ __align__(16) float g_o[(size_t)MM * FF];             // (T, B, F)

// ---------------------------------------------------------------------------
// Generic 128x128x(K=768) SGEMM:  C = A @ W^T + bias
// A: (M,768) row-major. W: (768,768) row-major (torch Linear weight).
// SCATTER=true: write to (B,H,T,D) layout (QKV). false: plain row-major (M,768).
// 256 threads, 8x8 microtile per thread, BK=8.
// ---------------------------------------------------------------------------
template<bool SCATTER>
__global__ __launch_bounds__(256) void gemm768_kernel(
    const float* __restrict__ A, const float* __restrict__ W,
    const float* __restrict__ bias, float* __restrict__ out)
{
    __shared__ __align__(16) float As[8][132];
    __shared__ __align__(16) float Bs[8][132];
    const int tid = threadIdx.x;
    const int m0 = blockIdx.x * 128;
    const int n0 = blockIdx.y * 128;
    const int lr = tid >> 1;
    const int lc = (tid & 1) * 4;
    const int tr = tid >> 4;
    const int tc = tid & 15;

    float acc[8][8] = {};
    const float* Ap = A + (size_t)(m0 + lr) * FF + lc;
    const float* Wp = W + (size_t)(n0 + lr) * FF + lc;

    for (int kt = 0; kt < FF; kt += 8) {
        float4 av = *(const float4*)(Ap + kt);
        float4 wv = *(const float4*)(Wp + kt);
        As[lc+0][lr] = av.x; As[lc+1][lr] = av.y; As[lc+2][lr] = av.z; As[lc+3][lr] = av.w;
        Bs[lc+0][lr] = wv.x; Bs[lc+1][lr] = wv.y; Bs[lc+2][lr] = wv.z; Bs[lc+3][lr] = wv.w;
        __syncthreads();
        #pragma unroll
        for (int k = 0; k < 8; k++) {
            float a[8], b[8];
            *(float4*)(a)   = *(const float4*)&As[k][tr*8];
            *(float4*)(a+4) = *(const float4*)&As[k][tr*8+4];
            *(float4*)(b)   = *(const float4*)&Bs[k][tc*8];
            *(float4*)(b+4) = *(const float4*)&Bs[k][tc*8+4];
            #pragma unroll
            for (int i = 0; i < 8; i++)
                #pragma unroll
                for (int j = 0; j < 8; j++)
                    acc[i][j] = fmaf(a[i], b[j], acc[i][j]);
        }
        __syncthreads();
    }

    #pragma unroll
    for (int i = 0; i < 8; i++) {
        const int m = m0 + tr*8 + i;
        #pragma unroll
        for (int jj = 0; jj < 2; jj++) {
            const int n = n0 + tc*8 + jj*4;
            float4 bv = *(const float4*)&bias[n];
            float4 o;
            o.x = acc[i][jj*4+0] + bv.x;
            o.y = acc[i][jj*4+1] + bv.y;
            o.z = acc[i][jj*4+2] + bv.z;
            o.w = acc[i][jj*4+3] + bv.w;
            if (SCATTER) {
                const int t = m >> 3, b = m & 7;      // m = t*B + b
                const int h = n >> 8, d = n & 255;    // n = h*256 + d
                *(float4*)&out[(((size_t)(b*HH + h))*TT + t)*DD + d] = o;
            } else {
                *(float4*)&out[(size_t)m*FF + n] = o;
            }
        }
    }
}

// ---------------------------------------------------------------------------
// Scores: per (b,h): S = Q @ K^T / 8.   M=N=2048, K=256.
// ---------------------------------------------------------------------------
__global__ __launch_bounds__(256) void scores_kernel()
{
    const int bh = blockIdx.z;
    const float* __restrict__ Q  = g_q + (size_t)bh * TT * DD;
    const float* __restrict__ Kp = g_k + (size_t)bh * TT * DD;
    float* __restrict__ S = g_s + (size_t)bh * TT * TT;

    __shared__ __align__(16) float As[8][132];
    __shared__ __align__(16) float Bs[8][132];
    const int tid = threadIdx.x;
    const int m0 = blockIdx.x * 128;
    const int n0 = blockIdx.y * 128;
    const int lr = tid >> 1;
    const int lc = (tid & 1) * 4;
    const int tr = tid >> 4;
    const int tc = tid & 15;

    float acc[8][8] = {};
    const float* Qp = Q  + (size_t)(m0 + lr) * DD + lc;
    const float* Kq = Kp + (size_t)(n0 + lr) * DD + lc;

    for (int kt = 0; kt < DD; kt += 8) {
        float4 av = *(const float4*)(Qp + kt);
        float4 bv = *(const float4*)(Kq + kt);
        As[lc+0][lr] = av.x; As[lc+1][lr] = av.y; As[lc+2][lr] = av.z; As[lc+3][lr] = av.w;
        Bs[lc+0][lr] = bv.x; Bs[lc+1][lr] = bv.y; Bs[lc+2][lr] = bv.z; Bs[lc+3][lr] = bv.w;
        __syncthreads();
        #pragma unroll
        for (int k = 0; k < 8; k++) {
            float a[8], b[8];
            *(float4*)(a)   = *(const float4*)&As[k][tr*8];
            *(float4*)(a+4) = *(const float4*)&As[k][tr*8+4];
            *(float4*)(b)   = *(const float4*)&Bs[k][tc*8];
            *(float4*)(b+4) = *(const float4*)&Bs[k][tc*8+4];
            #pragma unroll
            for (int i = 0; i < 8; i++)
                #pragma unroll
                for (int j = 0; j < 8; j++)
                    acc[i][j] = fmaf(a[i], b[j], acc[i][j]);
        }
        __syncthreads();
    }

    #pragma unroll
    for (int i = 0; i < 8; i++) {
        const int m = m0 + tr*8 + i;
        #pragma unroll
        for (int jj = 0; jj < 2; jj++) {
            const int n = n0 + tc*8 + jj*4;
            float4 o;
            o.x = acc[i][jj*4+0] * 0.125f;
            o.y = acc[i][jj*4+1] * 0.125f;
            o.z = acc[i][jj*4+2] * 0.125f;
            o.w = acc[i][jj*4+3] * 0.125f;
            *(float4*)&S[(size_t)m*TT + n] = o;
        }
    }
}

// ---------------------------------------------------------------------------
// Row softmax over last dim (2048). One block per row, 8 elems/thread.
// ---------------------------------------------------------------------------
__global__ __launch_bounds__(256) void softmax_kernel()
{
    const size_t base = (size_t)blockIdx.x * TT;
    const int tid = threadIdx.x;
    float v[8];
    float mx = -3.4e38f;
    #pragma unroll
    for (int i = 0; i < 8; i++) {
        v[i] = g_s[base + tid + i*256];
        mx = fmaxf(mx, v[i]);
    }
    #pragma unroll
    for (int o = 16; o; o >>= 1) mx = fmaxf(mx, __shfl_xor_sync(0xffffffffu, mx, o));
    __shared__ float redm[8];
    __shared__ float reds[8];
    if ((tid & 31) == 0) redm[tid >> 5] = mx;
    __syncthreads();
    float gm = redm[0];
    #pragma unroll
    for (int w = 1; w < 8; w++) gm = fmaxf(gm, redm[w]);

    float sm = 0.f;
    #pragma unroll
    for (int i = 0; i < 8; i++) { v[i] = __expf(v[i] - gm); sm += v[i]; }
    #pragma unroll
    for (int o = 16; o; o >>= 1) sm += __shfl_xor_sync(0xffffffffu, sm, o);
    if ((tid & 31) == 0) reds[tid >> 5] = sm;
    __syncthreads();
    float gs = 0.f;
    #pragma unroll
    for (int w = 0; w < 8; w++) gs += reds[w];
    const float inv = 1.f / gs;
    #pragma unroll
    for (int i = 0; i < 8; i++) g_s[base + tid + i*256] = v[i] * inv;
}

// ---------------------------------------------------------------------------
// AV: per (b,h): O = attn @ V.  M=2048, N=256, K=2048.
// Output scattered into (T,B,F) layout for the final projection.
// ---------------------------------------------------------------------------
__global__ __launch_bounds__(256) void av_kernel()
{
    const int bh = blockIdx.z;
    const int b = bh / HH;
    const int h = bh - b * HH;
    const float* __restrict__ S = g_s + (size_t)bh * TT * TT;
    const float* __restrict__ V = g_v + (size_t)bh * TT * DD;

    __shared__ __align__(16) float As[8][132];
    __shared__ __align__(16) float Bs[8][132];
    const int tid = threadIdx.x;
    const int m0 = blockIdx.x * 128;
    const int n0 = blockIdx.y * 128;
    const int lr = tid >> 1;
    const int lc = (tid & 1) * 4;
    const int vr = tid >> 5;            // V tile: 8 rows (k) x 128 cols (n)
    const int vc = (tid & 31) * 4;
    const int tr = tid >> 4;
    const int tc = tid & 15;

    float acc[8][8] = {};
    const float* Sp = S + (size_t)(m0 + lr) * TT + lc;

    for (int kt = 0; kt < TT; kt += 8) {
        float4 av = *(const float4*)(Sp + kt);
        As[lc+0][lr] = av.x; As[lc+1][lr] = av.y; As[lc+2][lr] = av.z; As[lc+3][lr] = av.w;
        float4 vv = *(const float4*)&V[(size_t)(kt + vr) * DD + n0 + vc];
        *(float4*)&Bs[vr][vc] = vv;
        __syncthreads();
        #pragma unroll
        for (int k = 0; k < 8; k++) {
            float a[8], b2[8];
            *(float4*)(a)    = *(const float4*)&As[k][tr*8];
            *(float4*)(a+4)  = *(const float4*)&As[k][tr*8+4];
            *(float4*)(b2)   = *(const float4*)&Bs[k][tc*8];
            *(float4*)(b2+4) = *(const float4*)&Bs[k][tc*8+4];
            #pragma unroll
            for (int i = 0; i < 8; i++)
                #pragma unroll
                for (int j = 0; j < 8; j++)
                    acc[i][j] = fmaf(a[i], b2[j], acc[i][j]);
        }
        __syncthreads();
    }

    #pragma unroll
    for (int i = 0; i < 8; i++) {
        const int t = m0 + tr*8 + i;
        #pragma unroll
        for (int jj = 0; jj < 2; jj++) {
            const int n = n0 + tc*8 + jj*4;  // n in [0,256) = d
            float4 o;
            o.x = acc[i][jj*4+0];
            o.y = acc[i][jj*4+1];
            o.z = acc[i][jj*4+2];
            o.w = acc[i][jj*4+3];
            *(float4*)&g_o[((size_t)t*BB + b)*FF + h*DD + n] = o;
        }
    }
}

// ---------------------------------------------------------------------------
extern "C" void kernel_launch(void* const* d_in, const int* in_sizes, int n_in,
                              void* d_out, int out_size)
{
    const float* x  = (const float*)d_in[0];
    const float* Wq = (const float*)d_in[1];
    const float* bq = (const float*)d_in[2];
    const float* Wk = (const float*)d_in[3];
    const float* bk = (const float*)d_in[4];
    const float* Wv = (const float*)d_in[5];
    const float* bv = (const float*)d_in[6];
    const float* Wo = (const float*)d_in[7];
    const float* bo = (const float*)d_in[8];
    float* out = (float*)d_out;

    float *pq, *pk, *pv, *po;
    cudaGetSymbolAddress((void**)&pq, g_q);
    cudaGetSymbolAddress((void**)&pk, g_k);
    cudaGetSymbolAddress((void**)&pv, g_v);
    cudaGetSymbolAddress((void**)&po, g_o);

    dim3 gProj(MM / 128, FF / 128);          // 128 x 6
    gemm768_kernel<true><<<gProj, 256>>>(x, Wq, bq, pq);
    gemm768_kernel<true><<<gProj, 256>>>(x, Wk, bk, pk);
    gemm768_kernel<true><<<gProj, 256>>>(x, Wv, bv, pv);

    dim3 gScores(TT / 128, TT / 128, BHN);   // 16 x 16 x 24
    scores_kernel<<<gScores, 256>>>();

    softmax_kernel<<<BHN * TT, 256>>>();     // 49152 rows

    dim3 gAV(TT / 128, DD / 128, BHN);       // 16 x 2 x 24
    av_kernel<<<gAV, 256>>>();

    gemm768_kernel<false><<<gProj, 256>>>(po, Wo, bo, out);
}

// round 3
// speedup vs baseline: 2.2857x; 2.2857x over previous
#include <cuda_runtime.h>
#include <cuda_bf16.h>
#include <cstdint>

#define TT 2048
#define BB 8
#define FD 768
#define HH 3
#define DH 256
#define MROWS (TT*BB)      // 16384
#define NBH (BB*HH)        // 24

// ------------------------- device scratch (static) -------------------------
__device__ __align__(16) __nv_bfloat16 g_xh[MROWS*FD], g_xl[MROWS*FD];
__device__ __align__(16) __nv_bfloat16 g_wqh[FD*FD], g_wql[FD*FD];
__device__ __align__(16) __nv_bfloat16 g_wkh[FD*FD], g_wkl[FD*FD];
__device__ __align__(16) __nv_bfloat16 g_wvh[FD*FD], g_wvl[FD*FD];
__device__ __align__(16) __nv_bfloat16 g_woh[FD*FD], g_wol[FD*FD];
__device__ __align__(16) __nv_bfloat16 g_qh[NBH*TT*DH], g_ql[NBH*TT*DH];
__device__ __align__(16) __nv_bfloat16 g_kh[NBH*TT*DH], g_kl[NBH*TT*DH];
__device__ __align__(16) float         g_vf[NBH*TT*DH];
__device__ __align__(16) __nv_bfloat16 g_vth[NBH*DH*TT], g_vtl[NBH*DH*TT];
__device__ __align__(16) float         g_s [(size_t)NBH*TT*TT];
__device__ __align__(16) __nv_bfloat16 g_sh[(size_t)NBH*TT*TT];
__device__ __align__(16) __nv_bfloat16 g_sl[(size_t)NBH*TT*TT];
__device__ __align__(16) __nv_bfloat16 g_oh[MROWS*FD], g_ol[MROWS*FD];

// ------------------------------ PTX helpers --------------------------------
__device__ __forceinline__ uint32_t smem_u32(const void* p) {
    uint32_t a;
    asm("{ .reg .u64 t; cvta.to.shared.u64 t, %1; cvt.u32.u64 %0, t; }" : "=r"(a) : "l"(p));
    return a;
}
#define CP16(dst, src) \
    asm volatile("cp.async.cg.shared.global [%0], [%1], 16;" :: "r"(dst), "l"(src) : "memory")
#define CP_COMMIT() asm volatile("cp.async.commit_group;" ::: "memory")
#define CP_WAIT1()  asm volatile("cp.async.wait_group 1;" ::: "memory")
#define CP_WAIT0()  asm volatile("cp.async.wait_group 0;" ::: "memory")

#define LDSM4(r0,r1,r2,r3,addr) \
    asm volatile("ldmatrix.sync.aligned.m8n8.x4.shared.b16 {%0,%1,%2,%3}, [%4];" \
        : "=r"(r0), "=r"(r1), "=r"(r2), "=r"(r3) : "r"(addr))

#define MMA16816(d, a, b0v, b1v) \
    asm volatile("mma.sync.aligned.m16n8k16.row.col.f32.bf16.bf16.f32 " \
        "{%0,%1,%2,%3}, {%4,%5,%6,%7}, {%8,%9}, {%0,%1,%2,%3};" \
        : "+f"((d)[0]), "+f"((d)[1]), "+f"((d)[2]), "+f"((d)[3]) \
        : "r"((a)[0]), "r"((a)[1]), "r"((a)[2]), "r"((a)[3]), "r"(b0v), "r"(b1v))

__device__ __forceinline__ void split2(float v, __nv_bfloat16& h, __nv_bfloat16& l) {
    h = __float2bfloat16(v);
    l = __float2bfloat16(v - __bfloat162float(h));
}

// ------------------- split-bf16 GEMM via mma.sync (HMMA) -------------------
// C[m,n] = sum_k A[m,k]*B[n,k], both operands K-major bf16 hi/lo pairs.
// Terms: Ah*Bh + Ah*Bl + Al*Bh.
// Tile: BM=128, BN=128, BK=32. 8 warps (2x4), warp tile 64x32.
// 3-stage cp.async pipeline. Rows padded to 80B (conflict-free ldmatrix).
#define BM 128
#define BN 128
#define BK 32
#define ROWB 80
#define MAT_BYTES (128*ROWB)          // 10240
#define STAGE_BYTES (4*MAT_BYTES)     // 40960: [Ah Al Bh Bl]
#define NSTAGE 3
#define SMEM_BYTES (NSTAGE*STAGE_BYTES)

enum { EPI_QK = 0, EPI_VF = 1, EPI_S = 2, EPI_AV = 3, EPI_OUT = 4 };

template<int EPI>
__global__ __launch_bounds__(256, 1) void gemm_mma(
    const __nv_bfloat16* __restrict__ Ah, const __nv_bfloat16* __restrict__ Al,
    const __nv_bfloat16* __restrict__ Bh, const __nv_bfloat16* __restrict__ Bl,
    const float* __restrict__ bias,
    float* __restrict__ outF, __nv_bfloat16* __restrict__ outH, __nv_bfloat16* __restrict__ outL,
    int K, long long sAz, long long sBz)
{
    extern __shared__ char smem[];
    const uint32_t sb = smem_u32(smem);

    const int tid = threadIdx.x;
    const int wid = tid >> 5, lane = tid & 31;
    const int wm = wid >> 2, wn = wid & 3;     // 2 x 4 warps
    const int z  = blockIdx.z;
    const int m0 = blockIdx.x * BM, n0 = blockIdx.y * BN;

    const __nv_bfloat16* pAh = Ah + (long long)z * sAz;
    const __nv_bfloat16* pAl = Al + (long long)z * sAz;
    const __nv_bfloat16* pBh = Bh + (long long)z * sBz;
    const __nv_bfloat16* pBl = Bl + (long long)z * sBz;

    float acc[4][4][4] = {};

    // per-thread load chunks: 512 x 16B per matrix, 2 per thread
    const int ci0 = tid, ci1 = tid + 256;
    const int r0l = ci0 >> 2, c0l = ci0 & 3;
    const int r1l = ci1 >> 2, c1l = ci1 & 3;

    auto load_stage = [&](int kb, int s) {
        const uint32_t st = sb + s * STAGE_BYTES;
        {
            size_t ga = (size_t)(m0 + r0l) * K + kb * BK + c0l * 8;
            size_t gb = (size_t)(n0 + r0l) * K + kb * BK + c0l * 8;
            uint32_t so = r0l * ROWB + c0l * 16;
            CP16(st + so,                 pAh + ga);
            CP16(st + MAT_BYTES + so,     pAl + ga);
            CP16(st + 2*MAT_BYTES + so,   pBh + gb);
            CP16(st + 3*MAT_BYTES + so,   pBl + gb);
        }
        {
            size_t ga = (size_t)(m0 + r1l) * K + kb * BK + c1l * 8;
            size_t gb = (size_t)(n0 + r1l) * K + kb * BK + c1l * 8;
            uint32_t so = r1l * ROWB + c1l * 16;
            CP16(st + so,                 pAh + ga);
            CP16(st + MAT_BYTES + so,     pAl + ga);
            CP16(st + 2*MAT_BYTES + so,   pBh + gb);
            CP16(st + 3*MAT_BYTES + so,   pBl + gb);
        }
    };

    const int NKB = K / BK;
    load_stage(0, 0); CP_COMMIT();
    if (NKB > 1) load_stage(1, 1);
    CP_COMMIT();

    // ldmatrix lane addressing
    const int a_row = wm * 64 + (lane & 7) + ((lane >> 3) & 1) * 8;   // + mf*16
    const int a_kb  = ((lane >> 4) & 1) * 16;                          // byte: +ks*32
    const int b_row = wn * 32 + (lane & 7) + (lane >= 16 ? 8 : 0);     // + nfp*16
    const int b_kb  = ((lane >> 3) & 1) * 16;                          // byte: +ks*32

    for (int kb = 0; kb < NKB; kb++) {
        CP_WAIT1();
        __syncthreads();
        if (kb + 2 < NKB) load_stage(kb + 2, (kb + 2) % NSTAGE);
        CP_COMMIT();

        const uint32_t st = sb + (kb % NSTAGE) * STAGE_BYTES;
        #pragma unroll
        for (int ks = 0; ks < 2; ks++) {
            uint32_t ah[4][4], al[4][4];
            uint32_t bh[2][4], bl[2][4];
            #pragma unroll
            for (int mf = 0; mf < 4; mf++) {
                uint32_t ao = (a_row + mf * 16) * ROWB + a_kb + ks * 32;
                LDSM4(ah[mf][0], ah[mf][1], ah[mf][2], ah[mf][3], st + ao);
                LDSM4(al[mf][0], al[mf][1], al[mf][2], al[mf][3], st + MAT_BYTES + ao);
            }
            #pragma unroll
            for (int np = 0; np < 2; np++) {
                uint32_t bo = (b_row + np * 16) * ROWB + b_kb + ks * 32;
                LDSM4(bh[np][0], bh[np][1], bh[np][2], bh[np][3], st + 2*MAT_BYTES + bo);
                LDSM4(bl[np][0], bl[np][1], bl[np][2], bl[np][3], st + 3*MAT_BYTES + bo);
            }
            #pragma unroll
            for (int mf = 0; mf < 4; mf++) {
                #pragma unroll
                for (int nf = 0; nf < 4; nf++) {
                    const int np = nf >> 1, hi = (nf & 1) * 2;
                    MMA16816(acc[mf][nf], ah[mf], bh[np][hi], bh[np][hi+1]);
                    MMA16816(acc[mf][nf], ah[mf], bl[np][hi], bl[np][hi+1]);
                    MMA16816(acc[mf][nf], al[mf], bh[np][hi], bh[np][hi+1]);
                }
            }
        }
        __syncthreads();
    }

    // ------------------------------- epilogue -------------------------------
    const int mrow = m0 + wm * 64 + (lane >> 2);
    const int ncol = n0 + wn * 32 + (lane & 3) * 2;

    #pragma unroll
    for (int mf = 0; mf < 4; mf++) {
        #pragma unroll
        for (int half = 0; half < 2; half++) {
            const int m = mrow + mf * 16 + half * 8;
            #pragma unroll
            for (int nf = 0; nf < 4; nf++) {
                const int n = ncol + nf * 8;
                float v0 = acc[mf][nf][half * 2];
                float v1 = acc[mf][nf][half * 2 + 1];

                if (EPI == EPI_QK) {
                    v0 += __ldg(&bias[n]);  v1 += __ldg(&bias[n + 1]);
                    const int t = m >> 3, b = m & 7, h = n >> 8, d = n & 255;
                    size_t o = ((size_t)(b * HH + h) * TT + t) * DH + d;
                    __nv_bfloat16 h0, l0, h1, l1; split2(v0, h0, l0); split2(v1, h1, l1);
                    __nv_bfloat162 ph; ph.x = h0; ph.y = h1;
                    __nv_bfloat162 pl; pl.x = l0; pl.y = l1;
                    *(__nv_bfloat162*)(outH + o) = ph;
                    *(__nv_bfloat162*)(outL + o) = pl;
                } else if (EPI == EPI_VF) {
                    v0 += __ldg(&bias[n]);  v1 += __ldg(&bias[n + 1]);
                    const int t = m >> 3, b = m & 7, h = n >> 8, d = n & 255;
                    size_t o = ((size_t)(b * HH + h) * TT + t) * DH + d;
                    float2 f; f.x = v0; f.y = v1;
                    *(float2*)(outF + o) = f;
                } else if (EPI == EPI_S) {
                    size_t o = ((size_t)z * TT + m) * TT + n;
                    float2 f; f.x = v0 * 0.125f; f.y = v1 * 0.125f;
                    *(float2*)(outF + o) = f;
                } else if (EPI == EPI_AV) {
                    const int b = z / HH, h = z % HH;
                    size_t o = ((size_t)m * BB + b) * FD + h * DH + n;
                    __nv_bfloat16 h0, l0, h1, l1; split2(v0, h0, l0); split2(v1, h1, l1);
                    __nv_bfloat162 ph; ph.x = h0; ph.y = h1;
                    __nv_bfloat162 pl; pl.x = l0; pl.y = l1;
                    *(__nv_bfloat162*)(outH + o) = ph;
                    *(__nv_bfloat162*)(outL + o) = pl;
                } else { // EPI_OUT
                    v0 += __ldg(&bias[n]);  v1 += __ldg(&bias[n + 1]);
                    size_t o = (size_t)m * FD + n;
                    float2 f; f.x = v0; f.y = v1;
                    *(float2*)(outF + o) = f;
                }
            }
        }
    }
}

// ------------------------------ helper kernels ------------------------------
__global__ __launch_bounds__(256) void split_kernel(
    const float* __restrict__ in, __nv_bfloat16* __restrict__ h,
    __nv_bfloat16* __restrict__ l, int n4)
{
    int i = blockIdx.x * 256 + threadIdx.x;
    if (i >= n4) return;
    float4 v = *(const float4*)(in + (size_t)i * 4);
    __nv_bfloat16 h0,l0,h1,l1,h2,l2,h3,l3;
    split2(v.x,h0,l0); split2(v.y,h1,l1); split2(v.z,h2,l2); split2(v.w,h3,l3);
    __nv_bfloat162 a; a.x=h0; a.y=h1; __nv_bfloat162 b; b.x=h2; b.y=h3;
    __nv_bfloat162 c; c.x=l0; c.y=l1; __nv_bfloat162 d; d.x=l2; d.y=l3;
    *(__nv_bfloat162*)(h + (size_t)i*4)     = a;
    *(__nv_bfloat162*)(h + (size_t)i*4 + 2) = b;
    *(__nv_bfloat162*)(l + (size_t)i*4)     = c;
    *(__nv_bfloat162*)(l + (size_t)i*4 + 2) = d;
}

// V (BH,T,D) fp32 -> Vt hi/lo (BH,D,T) bf16
__global__ __launch_bounds__(256) void vtrans_kernel()
{
    __shared__ float tl[32][33];
    const int bh = blockIdx.z;
    const int d0 = blockIdx.x * 32, t0 = blockIdx.y * 32;
    const int tx = threadIdx.x & 31, ty = threadIdx.x >> 5;  // 32 x 8
    const float* src = g_vf + ((size_t)bh * TT + t0) * DH + d0;
    #pragma unroll
    for (int i = 0; i < 4; i++)
        tl[ty + 8*i][tx] = src[(size_t)(ty + 8*i) * DH + tx];
    __syncthreads();
    #pragma unroll
    for (int i = 0; i < 4; i++) {
        int d = ty + 8*i;
        float v = tl[tx][d];
        __nv_bfloat16 h, l; split2(v, h, l);
        size_t o = ((size_t)bh * DH + d0 + d) * TT + t0 + tx;
        g_vth[o] = h; g_vtl[o] = l;
    }
}

// row softmax over S (fp32) -> Sh, Sl (bf16)
__global__ __launch_bounds__(256) void softmax_kernel()
{
    const size_t base = (size_t)blockIdx.x * TT;
    const int tid = threadIdx.x;
    float v[8];
    float mx = -3.4e38f;
    #pragma unroll
    for (int i = 0; i < 8; i++) { v[i] = g_s[base + tid + i*256]; mx = fmaxf(mx, v[i]); }
    #pragma unroll
    for (int o = 16; o; o >>= 1) mx = fmaxf(mx, __shfl_xor_sync(0xffffffffu, mx, o));
    __shared__ float redm[8], reds[8];
    if ((tid & 31) == 0) redm[tid >> 5] = mx;
    __syncthreads();
    float gm = redm[0];
    #pragma unroll
    for (int w = 1; w < 8; w++) gm = fmaxf(gm, redm[w]);
    float sm = 0.f;
    #pragma unroll
    for (int i = 0; i < 8; i++) { v[i] = __expf(v[i] - gm); sm += v[i]; }
    #pragma unroll
    for (int o = 16; o; o >>= 1) sm += __shfl_xor_sync(0xffffffffu, sm, o);
    if ((tid & 31) == 0) reds[tid >> 5] = sm;
    __syncthreads();
    float gs = 0.f;
    #pragma unroll
    for (int w = 0; w < 8; w++) gs += reds[w];
    const float inv = 1.f / gs;
    #pragma unroll
    for (int i = 0; i < 8; i++) {
        float p = v[i] * inv;
        __nv_bfloat16 h, l; split2(p, h, l);
        g_sh[base + tid + i*256] = h;
        g_sl[base + tid + i*256] = l;
    }
}

// --------------------------------- launch ----------------------------------
extern "C" void kernel_launch(void* const* d_in, const int* in_sizes, int n_in,
                              void* d_out, int out_size)
{
    const float* x  = (const float*)d_in[0];
    const float* Wq = (const float*)d_in[1];
    const float* bq = (const float*)d_in[2];
    const float* Wk = (const float*)d_in[3];
    const float* bk = (const float*)d_in[4];
    const float* Wv = (const float*)d_in[5];
    const float* bv = (const float*)d_in[6];
    const float* Wo = (const float*)d_in[7];
    const float* bo = (const float*)d_in[8];
    float* out = (float*)d_out;

    cudaFuncSetAttribute(gemm_mma<EPI_QK>,  cudaFuncAttributeMaxDynamicSharedMemorySize, SMEM_BYTES);
    cudaFuncSetAttribute(gemm_mma<EPI_VF>,  cudaFuncAttributeMaxDynamicSharedMemorySize, SMEM_BYTES);
    cudaFuncSetAttribute(gemm_mma<EPI_S>,   cudaFuncAttributeMaxDynamicSharedMemorySize, SMEM_BYTES);
    cudaFuncSetAttribute(gemm_mma<EPI_AV>,  cudaFuncAttributeMaxDynamicSharedMemorySize, SMEM_BYTES);
    cudaFuncSetAttribute(gemm_mma<EPI_OUT>, cudaFuncAttributeMaxDynamicSharedMemorySize, SMEM_BYTES);

    __nv_bfloat16 *xh,*xl,*wqh,*wql,*wkh,*wkl,*wvh,*wvl,*woh,*wol;
    __nv_bfloat16 *qh,*ql,*kh,*kl,*vth,*vtl,*sh,*sl,*oh,*ol;
    float *vf, *s;
    cudaGetSymbolAddress((void**)&xh, g_xh);  cudaGetSymbolAddress((void**)&xl, g_xl);
    cudaGetSymbolAddress((void**)&wqh, g_wqh); cudaGetSymbolAddress((void**)&wql, g_wql);
    cudaGetSymbolAddress((void**)&wkh, g_wkh); cudaGetSymbolAddress((void**)&wkl, g_wkl);
    cudaGetSymbolAddress((void**)&wvh, g_wvh); cudaGetSymbolAddress((void**)&wvl, g_wvl);
    cudaGetSymbolAddress((void**)&woh, g_woh); cudaGetSymbolAddress((void**)&wol, g_wol);
    cudaGetSymbolAddress((void**)&qh, g_qh);  cudaGetSymbolAddress((void**)&ql, g_ql);
    cudaGetSymbolAddress((void**)&kh, g_kh);  cudaGetSymbolAddress((void**)&kl, g_kl);
    cudaGetSymbolAddress((void**)&vf, g_vf);
    cudaGetSymbolAddress((void**)&vth, g_vth); cudaGetSymbolAddress((void**)&vtl, g_vtl);
    cudaGetSymbolAddress((void**)&s, g_s);
    cudaGetSymbolAddress((void**)&sh, g_sh);  cudaGetSymbolAddress((void**)&sl, g_sl);
    cudaGetSymbolAddress((void**)&oh, g_oh);  cudaGetSymbolAddress((void**)&ol, g_ol);

    // splits
    split_kernel<<<(MROWS*FD/4 + 255)/256, 256>>>(x,  xh,  xl,  MROWS*FD/4);
    split_kernel<<<(FD*FD/4 + 255)/256, 256>>>(Wq, wqh, wql, FD*FD/4);
    split_kernel<<<(FD*FD/4 + 255)/256, 256>>>(Wk, wkh, wkl, FD*FD/4);
    split_kernel<<<(FD*FD/4 + 255)/256, 256>>>(Wv, wvh, wvl, FD*FD/4);
    split_kernel<<<(FD*FD/4 + 255)/256, 256>>>(Wo, woh, wol, FD*FD/4);

    // projections  M=16384, N=768, K=768
    dim3 gP(MROWS/BM, FD/BN, 1);
    gemm_mma<EPI_QK><<<gP, 256, SMEM_BYTES>>>(xh, xl, wqh, wql, bq, nullptr, qh, ql, FD, 0, 0);
    gemm_mma<EPI_QK><<<gP, 256, SMEM_BYTES>>>(xh, xl, wkh, wkl, bk, nullptr, kh, kl, FD, 0, 0);
    gemm_mma<EPI_VF><<<gP, 256, SMEM_BYTES>>>(xh, xl, wvh, wvl, bv, vf, nullptr, nullptr, FD, 0, 0);

    // V transpose + split
    dim3 gT(DH/32, TT/32, NBH);
    vtrans_kernel<<<gT, 256>>>();

    // scores  per bh: M=N=2048, K=256
    dim3 gS(TT/BM, TT/BN, NBH);
    gemm_mma<EPI_S><<<gS, 256, SMEM_BYTES>>>(qh, ql, kh, kl, nullptr, s, nullptr, nullptr,
                                             DH, (long long)TT*DH, (long long)TT*DH);
    // softmax + split
    softmax_kernel<<<NBH*TT, 256>>>();

    // AV  per bh: M=2048, N=256, K=2048
    dim3 gA(TT/BM, DH/BN, NBH);
    gemm_mma<EPI_AV><<<gA, 256, SMEM_BYTES>>>(sh, sl, vth, vtl, nullptr, nullptr, oh, ol,
                                              TT, (long long)TT*TT, (long long)DH*TT);
    // output projection
    gemm_mma<EPI_OUT><<<gP, 256, SMEM_BYTES>>>(oh, ol, woh, wol, bo, out, nullptr, nullptr, FD, 0, 0);
}

// round 4
// speedup vs baseline: 2.6605x; 1.1640x over previous
#include <cuda_runtime.h>
#include <cuda_bf16.h>
#include <cstdint>

#define TT 2048
#define BB 8
#define FD 768
#define HH 3
#define DH 256
#define MROWS (TT*BB)      // 16384
#define NBH (BB*HH)        // 24

// ------------------------- device scratch (static) -------------------------
__device__ __align__(16) __nv_bfloat16 g_xh[MROWS*FD], g_xl[MROWS*FD];
__device__ __align__(16) __nv_bfloat16 g_wqh[FD*FD], g_wql[FD*FD];
__device__ __align__(16) __nv_bfloat16 g_wkh[FD*FD], g_wkl[FD*FD];
__device__ __align__(16) __nv_bfloat16 g_wvh[FD*FD], g_wvl[FD*FD];
__device__ __align__(16) __nv_bfloat16 g_woh[FD*FD], g_wol[FD*FD];
__device__ __align__(16) __nv_bfloat16 g_qh[NBH*TT*DH], g_ql[NBH*TT*DH];
__device__ __align__(16) __nv_bfloat16 g_kh[NBH*TT*DH], g_kl[NBH*TT*DH];
__device__ __align__(16) float         g_vf[NBH*TT*DH];
__device__ __align__(16) __nv_bfloat16 g_vth[NBH*DH*TT], g_vtl[NBH*DH*TT];
__device__ __align__(16) __nv_bfloat16 g_oh[MROWS*FD], g_ol[MROWS*FD];

// ------------------------------ PTX helpers --------------------------------
__device__ __forceinline__ uint32_t smem_u32(const void* p) {
    uint32_t a;
    asm("{ .reg .u64 t; cvta.to.shared.u64 t, %1; cvt.u32.u64 %0, t; }" : "=r"(a) : "l"(p));
    return a;
}
#define CP16(dst, src) \
    asm volatile("cp.async.cg.shared.global [%0], [%1], 16;" :: "r"(dst), "l"(src) : "memory")
#define CP_COMMIT() asm volatile("cp.async.commit_group;" ::: "memory")
#define CP_WAIT0()  asm volatile("cp.async.wait_group 0;" ::: "memory")
#define CP_WAIT1()  asm volatile("cp.async.wait_group 1;" ::: "memory")
#define CP_WAIT2()  asm volatile("cp.async.wait_group 2;" ::: "memory")

#define LDSM4(r0,r1,r2,r3,addr) \
    asm volatile("ldmatrix.sync.aligned.m8n8.x4.shared.b16 {%0,%1,%2,%3}, [%4];" \
        : "=r"(r0), "=r"(r1), "=r"(r2), "=r"(r3) : "r"(addr))

#define MMA16816(d, a, b0v, b1v) \
    asm volatile("mma.sync.aligned.m16n8k16.row.col.f32.bf16.bf16.f32 " \
        "{%0,%1,%2,%3}, {%4,%5,%6,%7}, {%8,%9}, {%0,%1,%2,%3};" \
        : "+f"((d)[0]), "+f"((d)[1]), "+f"((d)[2]), "+f"((d)[3]) \
        : "r"((a)[0]), "r"((a)[1]), "r"((a)[2]), "r"((a)[3]), "r"(b0v), "r"(b1v))

#define SWZ(o) ((uint32_t)(o) ^ ((((uint32_t)(o)) >> 3) & 0x70))

__device__ __forceinline__ void split2(float v, __nv_bfloat16& h, __nv_bfloat16& l) {
    h = __float2bfloat16(v);
    l = __float2bfloat16(v - __bfloat162float(h));
}

// ------------------- split-bf16 GEMM via mma.sync (HMMA) -------------------
#define BM 128
#define BN 128
#define BK 32
#define ROWB 80
#define MAT_BYTES (128*ROWB)
#define STAGE_BYTES (4*MAT_BYTES)
#define NSTAGE 3
#define SMEM_BYTES (NSTAGE*STAGE_BYTES)

enum { EPI_QK = 0, EPI_VF = 1, EPI_OUT = 2 };

template<int EPI>
__global__ __launch_bounds__(256, 1) void gemm_mma(
    const __nv_bfloat16* __restrict__ Ah, const __nv_bfloat16* __restrict__ Al,
    const __nv_bfloat16* __restrict__ Bh, const __nv_bfloat16* __restrict__ Bl,
    const float* __restrict__ bias,
    float* __restrict__ outF, __nv_bfloat16* __restrict__ outH, __nv_bfloat16* __restrict__ outL,
    int K, float oscale)
{
    extern __shared__ char smem[];
    const uint32_t sb = smem_u32(smem);

    const int tid = threadIdx.x;
    const int wid = tid >> 5, lane = tid & 31;
    const int wm = wid >> 2, wn = wid & 3;
    const int m0 = blockIdx.x * BM, n0 = blockIdx.y * BN;

    float acc[4][4][4] = {};

    const int ci0 = tid, ci1 = tid + 256;
    const int r0l = ci0 >> 2, c0l = ci0 & 3;
    const int r1l = ci1 >> 2, c1l = ci1 & 3;

    auto load_stage = [&](int kb, int s) {
        const uint32_t st = sb + s * STAGE_BYTES;
        {
            size_t ga = (size_t)(m0 + r0l) * K + kb * BK + c0l * 8;
            size_t gb = (size_t)(n0 + r0l) * K + kb * BK + c0l * 8;
            uint32_t so = r0l * ROWB + c0l * 16;
            CP16(st + so,                 Ah + ga);
            CP16(st + MAT_BYTES + so,     Al + ga);
            CP16(st + 2*MAT_BYTES + so,   Bh + gb);
            CP16(st + 3*MAT_BYTES + so,   Bl + gb);
        }
        {
            size_t ga = (size_t)(m0 + r1l) * K + kb * BK + c1l * 8;
            size_t gb = (size_t)(n0 + r1l) * K + kb * BK + c1l * 8;
            uint32_t so = r1l * ROWB + c1l * 16;
            CP16(st + so,                 Ah + ga);
            CP16(st + MAT_BYTES + so,     Al + ga);
            CP16(st + 2*MAT_BYTES + so,   Bh + gb);
            CP16(st + 3*MAT_BYTES + so,   Bl + gb);
        }
    };

    const int NKB = K / BK;
    load_stage(0, 0); CP_COMMIT();
    if (NKB > 1) load_stage(1, 1);
    CP_COMMIT();

    const int a_row = wm * 64 + (lane & 7) + ((lane >> 3) & 1) * 8;
    const int a_kb  = ((lane >> 4) & 1) * 16;
    const int b_row = wn * 32 + (lane & 7) + (lane >= 16 ? 8 : 0);
    const int b_kb  = ((lane >> 3) & 1) * 16;

    for (int kb = 0; kb < NKB; kb++) {
        CP_WAIT1();
        __syncthreads();
        if (kb + 2 < NKB) load_stage(kb + 2, (kb + 2) % NSTAGE);
        CP_COMMIT();

        const uint32_t st = sb + (kb % NSTAGE) * STAGE_BYTES;
        #pragma unroll
        for (int ks = 0; ks < 2; ks++) {
            uint32_t ah[4][4], al[4][4];
            uint32_t bh[2][4], bl[2][4];
            #pragma unroll
            for (int mf = 0; mf < 4; mf++) {
                uint32_t ao = (a_row + mf * 16) * ROWB + a_kb + ks * 32;
                LDSM4(ah[mf][0], ah[mf][1], ah[mf][2], ah[mf][3], st + ao);
                LDSM4(al[mf][0], al[mf][1], al[mf][2], al[mf][3], st + MAT_BYTES + ao);
            }
            #pragma unroll
            for (int np = 0; np < 2; np++) {
                uint32_t bo = (b_row + np * 16) * ROWB + b_kb + ks * 32;
                LDSM4(bh[np][0], bh[np][1], bh[np][2], bh[np][3], st + 2*MAT_BYTES + bo);
                LDSM4(bl[np][0], bl[np][1], bl[np][2], bl[np][3], st + 3*MAT_BYTES + bo);
            }
            #pragma unroll
            for (int mf = 0; mf < 4; mf++) {
                #pragma unroll
                for (int nf = 0; nf < 4; nf++) {
                    const int np = nf >> 1, hi = (nf & 1) * 2;
                    MMA16816(acc[mf][nf], ah[mf], bh[np][hi], bh[np][hi+1]);
                    MMA16816(acc[mf][nf], ah[mf], bl[np][hi], bl[np][hi+1]);
                    MMA16816(acc[mf][nf], al[mf], bh[np][hi], bh[np][hi+1]);
                }
            }
        }
        __syncthreads();
    }

    const int mrow = m0 + wm * 64 + (lane >> 2);
    const int ncol = n0 + wn * 32 + (lane & 3) * 2;

    #pragma unroll
    for (int mf = 0; mf < 4; mf++) {
        #pragma unroll
        for (int half = 0; half < 2; half++) {
            const int m = mrow + mf * 16 + half * 8;
            #pragma unroll
            for (int nf = 0; nf < 4; nf++) {
                const int n = ncol + nf * 8;
                float v0 = acc[mf][nf][half * 2];
                float v1 = acc[mf][nf][half * 2 + 1];

                if (EPI == EPI_QK) {
                    v0 = (v0 + __ldg(&bias[n])) * oscale;
                    v1 = (v1 + __ldg(&bias[n + 1])) * oscale;
                    const int t = m >> 3, b = m & 7, h = n >> 8, d = n & 255;
                    size_t o = ((size_t)(b * HH + h) * TT + t) * DH + d;
                    __nv_bfloat16 h0, l0, h1, l1; split2(v0, h0, l0); split2(v1, h1, l1);
                    __nv_bfloat162 ph; ph.x = h0; ph.y = h1;
                    __nv_bfloat162 pl; pl.x = l0; pl.y = l1;
                    *(__nv_bfloat162*)(outH + o) = ph;
                    *(__nv_bfloat162*)(outL + o) = pl;
                } else if (EPI == EPI_VF) {
                    v0 += __ldg(&bias[n]);  v1 += __ldg(&bias[n + 1]);
                    const int t = m >> 3, b = m & 7, h = n >> 8, d = n & 255;
                    size_t o = ((size_t)(b * HH + h) * TT + t) * DH + d;
                    float2 f; f.x = v0; f.y = v1;
                    *(float2*)(outF + o) = f;
                } else { // EPI_OUT
                    v0 += __ldg(&bias[n]);  v1 += __ldg(&bias[n + 1]);
                    size_t o = (size_t)m * FD + n;
                    float2 f; f.x = v0; f.y = v1;
                    *(float2*)(outF + o) = f;
                }
            }
        }
    }
}

// --------------------------- fused flash attention --------------------------
// Per CTA: 64 q-rows (one bh), loop over 32 kv-tiles of 64.
// smem (swizzled 128B-row 64x64 bf16 mats, 8KB each):
//  Q: 8 mats (4 k-chunks x h/l)      @ 0      (64KB)
//  K: 2 bufs x 2 (h/l)               @ 65536  (32KB)
//  V: 4 quarters x 2 (h/l)           @ 98304  (64KB)
//  P: 2 (h/l)                        @ 163840 (16KB)
//  redmax/redsum: 2x[2][64] floats   @ 180224
#define AMAT 8192
#define Q_OFF 0
#define KB_OFF 65536
#define V_OFF 98304
#define P_OFF 163840
#define RMAX_OFF 180224
#define RSUM_OFF 180736
#define ATT_SMEM 181248
#define NTILE (TT/64)   // 32

__global__ __launch_bounds__(256, 1) void attn_kernel()
{
    extern __shared__ char sm[];
    const uint32_t sb = smem_u32(sm);
    const int tid = threadIdx.x, lane = tid & 31, wid = tid >> 5;
    const int wm = wid & 3, wn = wid >> 2;             // 4 x 2 warp grid
    const int bh = blockIdx.y, m0 = blockIdx.x * 64;

    // ---- async load helpers ----
    auto load_k = [&](int tile, int j, int buf) {
        const uint32_t dh = sb + KB_OFF + (buf * 2) * AMAT;
        const int n0 = tile * 64;
        #pragma unroll
        for (int i = 0; i < 2; i++) {
            int ci = tid + i * 256;
            int r = ci >> 3, c = ci & 7;
            size_t g = ((size_t)bh * TT + n0 + r) * DH + j * 64 + c * 8;
            uint32_t so = SWZ(r * 128 + c * 16);
            CP16(dh + so,        g_kh + g);
            CP16(dh + AMAT + so, g_kl + g);
        }
    };
    auto load_v = [&](int tile, int q) {
        const uint32_t dh = sb + V_OFF + (q * 2) * AMAT;
        const int n0 = tile * 64;
        #pragma unroll
        for (int i = 0; i < 2; i++) {
            int ci = tid + i * 256;
            int r = ci >> 3, c = ci & 7;
            size_t g = ((size_t)bh * DH + q * 64 + r) * TT + n0 + c * 8;
            uint32_t so = SWZ(r * 128 + c * 16);
            CP16(dh + so,        g_vth + g);
            CP16(dh + AMAT + so, g_vtl + g);
        }
    };

    // ---- prologue: Q resident + first K chunks + first V halves ----
    #pragma unroll
    for (int i = 0; i < 16; i++) {
        int ci = tid + i * 256;
        int mat = ci >> 9, w = ci & 511, r = w >> 3, c = w & 7;
        int j = mat >> 1, hl = mat & 1;
        size_t g = ((size_t)bh * TT + m0 + r) * DH + j * 64 + c * 8;
        const __nv_bfloat16* src = hl ? g_ql : g_qh;
        CP16(sb + Q_OFF + mat * AMAT + SWZ(r * 128 + c * 16), src + g);
    }
    CP_COMMIT();
    load_k(0, 0, 0); CP_COMMIT();
    load_k(0, 1, 1); CP_COMMIT();
    load_v(0, 0); load_v(0, 1); CP_COMMIT();

    // ---- ldmatrix lane addressing ----
    const int a_rl = (lane & 7) + ((lane >> 3) & 1) * 8;   // A-operand row-in-16
    const int a_kb = ((lane >> 4) & 1) * 16;
    const int b_rl = (lane & 7) + (lane >= 16 ? 8 : 0);    // B-operand row-in-16
    const int b_kb = ((lane >> 3) & 1) * 16;

    auto qk_chunk = [&](int j, int buf, float (*sacc)[4]) {
        const uint32_t qm = sb + Q_OFF + (j * 2) * AMAT;
        const uint32_t km = sb + KB_OFF + (buf * 2) * AMAT;
        #pragma unroll
        for (int ks = 0; ks < 4; ks++) {
            uint32_t qh[4], ql[4];
            uint32_t ao = SWZ((wm * 16 + a_rl) * 128 + a_kb + ks * 32);
            LDSM4(qh[0], qh[1], qh[2], qh[3], qm + ao);
            LDSM4(ql[0], ql[1], ql[2], ql[3], qm + AMAT + ao);
            #pragma unroll
            for (int g = 0; g < 2; g++) {
                uint32_t kh[4], kl[4];
                uint32_t bo = SWZ((wn * 32 + g * 16 + b_rl) * 128 + b_kb + ks * 32);
                LDSM4(kh[0], kh[1], kh[2], kh[3], km + bo);
                LDSM4(kl[0], kl[1], kl[2], kl[3], km + AMAT + bo);
                MMA16816(sacc[g*2],   qh, kh[0], kh[1]);
                MMA16816(sacc[g*2],   qh, kl[0], kl[1]);
                MMA16816(sacc[g*2],   ql, kh[0], kh[1]);
                MMA16816(sacc[g*2+1], qh, kh[2], kh[3]);
                MMA16816(sacc[g*2+1], qh, kl[2], kl[3]);
                MMA16816(sacc[g*2+1], ql, kh[2], kh[3]);
            }
        }
    };

    // ---- state ----
    float oacc[16][4] = {};
    float mrun0 = -1e30f, mrun1 = -1e30f, lrun0 = 0.f, lrun1 = 0.f;
    const int r0 = wm * 16 + (lane >> 2), r1 = r0 + 8;
    float* rmax = (float*)(sm + RMAX_OFF);
    float* rsum = (float*)(sm + RSUM_OFF);

    for (int tile = 0; tile < NTILE; tile++) {
        float sacc[4][4] = {};

        // j=0
        CP_WAIT2(); __syncthreads();
        qk_chunk(0, 0, sacc);
        __syncthreads();
        load_k(tile, 2, 0); load_v(tile, 2); CP_COMMIT();
        // j=1
        CP_WAIT2(); __syncthreads();
        qk_chunk(1, 1, sacc);
        __syncthreads();
        load_k(tile, 3, 1); load_v(tile, 3); CP_COMMIT();
        // j=2
        CP_WAIT1(); __syncthreads();
        qk_chunk(2, 0, sacc);
        __syncthreads();
        if (tile + 1 < NTILE) load_k(tile + 1, 0, 0);
        CP_COMMIT();
        // j=3
        CP_WAIT1(); __syncthreads();
        qk_chunk(3, 1, sacc);
        __syncthreads();
        if (tile + 1 < NTILE) load_k(tile + 1, 1, 1);
        CP_COMMIT();

        // ---- online softmax ----
        float mx0 = -1e30f, mx1 = -1e30f;
        #pragma unroll
        for (int nf = 0; nf < 4; nf++) {
            mx0 = fmaxf(mx0, fmaxf(sacc[nf][0], sacc[nf][1]));
            mx1 = fmaxf(mx1, fmaxf(sacc[nf][2], sacc[nf][3]));
        }
        mx0 = fmaxf(mx0, __shfl_xor_sync(0xffffffffu, mx0, 1));
        mx0 = fmaxf(mx0, __shfl_xor_sync(0xffffffffu, mx0, 2));
        mx1 = fmaxf(mx1, __shfl_xor_sync(0xffffffffu, mx1, 1));
        mx1 = fmaxf(mx1, __shfl_xor_sync(0xffffffffu, mx1, 2));
        if ((lane & 3) == 0) { rmax[wn * 64 + r0] = mx0; rmax[wn * 64 + r1] = mx1; }
        __syncthreads();

        float mn0 = fmaxf(mrun0, fmaxf(rmax[r0], rmax[64 + r0]));
        float mn1 = fmaxf(mrun1, fmaxf(rmax[r1], rmax[64 + r1]));
        float a0 = __expf(mrun0 - mn0), a1 = __expf(mrun1 - mn1);
        mrun0 = mn0; mrun1 = mn1;

        float s0 = 0.f, s1 = 0.f;
        #pragma unroll
        for (int nf = 0; nf < 4; nf++) {
            sacc[nf][0] = __expf(sacc[nf][0] - mn0);
            sacc[nf][1] = __expf(sacc[nf][1] - mn0);
            sacc[nf][2] = __expf(sacc[nf][2] - mn1);
            sacc[nf][3] = __expf(sacc[nf][3] - mn1);
            s0 += sacc[nf][0] + sacc[nf][1];
            s1 += sacc[nf][2] + sacc[nf][3];
        }
        s0 += __shfl_xor_sync(0xffffffffu, s0, 1);
        s0 += __shfl_xor_sync(0xffffffffu, s0, 2);
        s1 += __shfl_xor_sync(0xffffffffu, s1, 1);
        s1 += __shfl_xor_sync(0xffffffffu, s1, 2);
        if ((lane & 3) == 0) { rsum[wn * 64 + r0] = s0; rsum[wn * 64 + r1] = s1; }

        // rescale O accumulators
        #pragma unroll
        for (int nf = 0; nf < 16; nf++) {
            oacc[nf][0] *= a0; oacc[nf][1] *= a0;
            oacc[nf][2] *= a1; oacc[nf][3] *= a1;
        }

        // write P (bf16 hi/lo) to smem
        #pragma unroll
        for (int nf = 0; nf < 4; nf++) {
            int c = wn * 32 + nf * 8 + (lane & 3) * 2;
            __nv_bfloat16 h0, l0, h1, l1;
            split2(sacc[nf][0], h0, l0); split2(sacc[nf][1], h1, l1);
            __nv_bfloat162 ph; ph.x = h0; ph.y = h1;
            __nv_bfloat162 pl; pl.x = l0; pl.y = l1;
            uint32_t off = SWZ(r0 * 128 + c * 2);
            *(__nv_bfloat162*)(sm + P_OFF + off) = ph;
            *(__nv_bfloat162*)(sm + P_OFF + AMAT + off) = pl;
            split2(sacc[nf][2], h0, l0); split2(sacc[nf][3], h1, l1);
            ph.x = h0; ph.y = h1; pl.x = l0; pl.y = l1;
            off = SWZ(r1 * 128 + c * 2);
            *(__nv_bfloat162*)(sm + P_OFF + off) = ph;
            *(__nv_bfloat162*)(sm + P_OFF + AMAT + off) = pl;
        }
        __syncthreads();

        lrun0 = lrun0 * a0 + rsum[r0] + rsum[64 + r0];
        lrun1 = lrun1 * a1 + rsum[r1] + rsum[64 + r1];

        // ---- AV: O += P * V ----
        {
            const uint32_t pm = sb + P_OFF;
            #pragma unroll
            for (int ks = 0; ks < 4; ks++) {
                uint32_t ph[4], pl[4];
                uint32_t ao = SWZ((wm * 16 + a_rl) * 128 + a_kb + ks * 32);
                LDSM4(ph[0], ph[1], ph[2], ph[3], pm + ao);
                LDSM4(pl[0], pl[1], pl[2], pl[3], pm + AMAT + ao);
                #pragma unroll
                for (int g = 0; g < 8; g++) {
                    const int q = wn * 2 + (g >> 2), dr = (g & 3) * 16;
                    const uint32_t vm = sb + V_OFF + (q * 2) * AMAT;
                    uint32_t bo = SWZ((dr + b_rl) * 128 + b_kb + ks * 32);
                    uint32_t vh[4], vl[4];
                    LDSM4(vh[0], vh[1], vh[2], vh[3], vm + bo);
                    LDSM4(vl[0], vl[1], vl[2], vl[3], vm + AMAT + bo);
                    MMA16816(oacc[g*2],   ph, vh[0], vh[1]);
                    MMA16816(oacc[g*2],   ph, vl[0], vl[1]);
                    MMA16816(oacc[g*2],   pl, vh[0], vh[1]);
                    MMA16816(oacc[g*2+1], ph, vh[2], vh[3]);
                    MMA16816(oacc[g*2+1], ph, vl[2], vl[3]);
                    MMA16816(oacc[g*2+1], pl, vh[2], vh[3]);
                }
            }
        }
        __syncthreads();
        if (tile + 1 < NTILE) { load_v(tile + 1, 0); load_v(tile + 1, 1); }
        CP_COMMIT();
    }

    // ---- epilogue: normalize + write hi/lo for output projection ----
    const int bb = bh / HH, hh = bh % HH;
    const float inv0 = 1.f / lrun0, inv1 = 1.f / lrun1;
    #pragma unroll
    for (int nf = 0; nf < 16; nf++) {
        int d = wn * 128 + nf * 8 + (lane & 3) * 2;
        {
            int t = m0 + r0;
            float v0 = oacc[nf][0] * inv0, v1 = oacc[nf][1] * inv0;
            size_t o = ((size_t)t * BB + bb) * FD + hh * DH + d;
            __nv_bfloat16 h0, l0, h1, l1; split2(v0, h0, l0); split2(v1, h1, l1);
            __nv_bfloat162 ph; ph.x = h0; ph.y = h1;
            __nv_bfloat162 pl; pl.x = l0; pl.y = l1;
            *(__nv_bfloat162*)(g_oh + o) = ph;
            *(__nv_bfloat162*)(g_ol + o) = pl;
        }
        {
            int t = m0 + r1;
            float v0 = oacc[nf][2] * inv1, v1 = oacc[nf][3] * inv1;
            size_t o = ((size_t)t * BB + bb) * FD + hh * DH + d;
            __nv_bfloat16 h0, l0, h1, l1; split2(v0, h0, l0); split2(v1, h1, l1);
            __nv_bfloat162 ph; ph.x = h0; ph.y = h1;
            __nv_bfloat162 pl; pl.x = l0; pl.y = l1;
            *(__nv_bfloat162*)(g_oh + o) = ph;
            *(__nv_bfloat162*)(g_ol + o) = pl;
        }
    }
}

// ------------------------------ helper kernels ------------------------------
__global__ __launch_bounds__(256) void split_kernel(
    const float* __restrict__ in, __nv_bfloat16* __restrict__ h,
    __nv_bfloat16* __restrict__ l, int n4)
{
    int i = blockIdx.x * 256 + threadIdx.x;
    if (i >= n4) return;
    float4 v = *(const float4*)(in + (size_t)i * 4);
    __nv_bfloat16 h0,l0,h1,l1,h2,l2,h3,l3;
    split2(v.x,h0,l0); split2(v.y,h1,l1); split2(v.z,h2,l2); split2(v.w,h3,l3);
    __nv_bfloat162 a; a.x=h0; a.y=h1; __nv_bfloat162 b; b.x=h2; b.y=h3;
    __nv_bfloat162 c; c.x=l0; c.y=l1; __nv_bfloat162 d; d.x=l2; d.y=l3;
    *(__nv_bfloat162*)(h + (size_t)i*4)     = a;
    *(__nv_bfloat162*)(h + (size_t)i*4 + 2) = b;
    *(__nv_bfloat162*)(l + (size_t)i*4)     = c;
    *(__nv_bfloat162*)(l + (size_t)i*4 + 2) = d;
}

// V (BH,T,D) fp32 -> Vt hi/lo (BH,D,T) bf16
__global__ __launch_bounds__(256) void vtrans_kernel()
{
    __shared__ float tl[32][33];
    const int bh = blockIdx.z;
    const int d0 = blockIdx.x * 32, t0 = blockIdx.y * 32;
    const int tx = threadIdx.x & 31, ty = threadIdx.x >> 5;
    const float* src = g_vf + ((size_t)bh * TT + t0) * DH + d0;
    #pragma unroll
    for (int i = 0; i < 4; i++)
        tl[ty + 8*i][tx] = src[(size_t)(ty + 8*i) * DH + tx];
    __syncthreads();
    #pragma unroll
    for (int i = 0; i < 4; i++) {
        int d = ty + 8*i;
        float v = tl[tx][d];
        __nv_bfloat16 h, l; split2(v, h, l);
        size_t o = ((size_t)bh * DH + d0 + d) * TT + t0 + tx;
        g_vth[o] = h; g_vtl[o] = l;
    }
}

// --------------------------------- launch ----------------------------------
extern "C" void kernel_launch(void* const* d_in, const int* in_sizes, int n_in,
                              void* d_out, int out_size)
{
    const float* x  = (const float*)d_in[0];
    const float* Wq = (const float*)d_in[1];
    const float* bq = (const float*)d_in[2];
    const float* Wk = (const float*)d_in[3];
    const float* bk = (const float*)d_in[4];
    const float* Wv = (const float*)d_in[5];
    const float* bv = (const float*)d_in[6];
    const float* Wo = (const float*)d_in[7];
    const float* bo = (const float*)d_in[8];
    float* out = (float*)d_out;

    cudaFuncSetAttribute(gemm_mma<EPI_QK>,  cudaFuncAttributeMaxDynamicSharedMemorySize, SMEM_BYTES);
    cudaFuncSetAttribute(gemm_mma<EPI_VF>,  cudaFuncAttributeMaxDynamicSharedMemorySize, SMEM_BYTES);
    cudaFuncSetAttribute(gemm_mma<EPI_OUT>, cudaFuncAttributeMaxDynamicSharedMemorySize, SMEM_BYTES);
    cudaFuncSetAttribute(attn_kernel,       cudaFuncAttributeMaxDynamicSharedMemorySize, ATT_SMEM);

    __nv_bfloat16 *xh,*xl,*wqh,*wql,*wkh,*wkl,*wvh,*wvl,*woh,*wol;
    __nv_bfloat16 *qh,*ql,*kh,*kl,*oh,*ol;
    float *vf;
    cudaGetSymbolAddress((void**)&xh, g_xh);  cudaGetSymbolAddress((void**)&xl, g_xl);
    cudaGetSymbolAddress((void**)&wqh, g_wqh); cudaGetSymbolAddress((void**)&wql, g_wql);
    cudaGetSymbolAddress((void**)&wkh, g_wkh); cudaGetSymbolAddress((void**)&wkl, g_wkl);
    cudaGetSymbolAddress((void**)&wvh, g_wvh); cudaGetSymbolAddress((void**)&wvl, g_wvl);
    cudaGetSymbolAddress((void**)&woh, g_woh); cudaGetSymbolAddress((void**)&wol, g_wol);
    cudaGetSymbolAddress((void**)&qh, g_qh);  cudaGetSymbolAddress((void**)&ql, g_ql);
    cudaGetSymbolAddress((void**)&kh, g_kh);  cudaGetSymbolAddress((void**)&kl, g_kl);
    cudaGetSymbolAddress((void**)&vf, g_vf);
    cudaGetSymbolAddress((void**)&oh, g_oh);  cudaGetSymbolAddress((void**)&ol, g_ol);

    // splits
    split_kernel<<<(MROWS*FD/4 + 255)/256, 256>>>(x,  xh,  xl,  MROWS*FD/4);
    split_kernel<<<(FD*FD/4 + 255)/256, 256>>>(Wq, wqh, wql, FD*FD/4);
    split_kernel<<<(FD*FD/4 + 255)/256, 256>>>(Wk, wkh, wkl, FD*FD/4);
    split_kernel<<<(FD*FD/4 + 255)/256, 256>>>(Wv, wvh, wvl, FD*FD/4);
    split_kernel<<<(FD*FD/4 + 255)/256, 256>>>(Wo, woh, wol, FD*FD/4);

    // projections  M=16384, N=768, K=768  (Q gets 1/8 scale folded in)
    dim3 gP(MROWS/BM, FD/BN);
    gemm_mma<EPI_QK><<<gP, 256, SMEM_BYTES>>>(xh, xl, wqh, wql, bq, nullptr, qh, ql, FD, 0.125f);
    gemm_mma<EPI_QK><<<gP, 256, SMEM_BYTES>>>(xh, xl, wkh, wkl, bk, nullptr, kh, kl, FD, 1.0f);
    gemm_mma<EPI_VF><<<gP, 256, SMEM_BYTES>>>(xh, xl, wvh, wvl, bv, vf, nullptr, nullptr, FD, 1.0f);

    // V transpose + split
    dim3 gT(DH/32, TT/32, NBH);
    vtrans_kernel<<<gT, 256>>>();

    // fused attention
    dim3 gA(TT/64, NBH);
    attn_kernel<<<gA, 256, ATT_SMEM>>>();

    // output projection
    gemm_mma<EPI_OUT><<<gP, 256, SMEM_BYTES>>>(oh, ol, woh, wol, bo, out, nullptr, nullptr, FD, 1.0f);
}

// round 5
// speedup vs baseline: 2.7932x; 1.0499x over previous
#include <cuda_runtime.h>
#include <cuda_bf16.h>
#include <cstdint>

#define TT 2048
#define BB 8
#define FD 768
#define HH 3
#define DH 256
#define MROWS (TT*BB)      // 16384
#define NBH (BB*HH)        // 24

// ------------------------- device scratch (static) -------------------------
__device__ __align__(16) __nv_bfloat16 g_xh[MROWS*FD], g_xl[MROWS*FD];
__device__ __align__(16) __nv_bfloat16 g_wqh[FD*FD], g_wql[FD*FD];
__device__ __align__(16) __nv_bfloat16 g_wkh[FD*FD], g_wkl[FD*FD];
__device__ __align__(16) __nv_bfloat16 g_wvh[FD*FD], g_wvl[FD*FD];
__device__ __align__(16) __nv_bfloat16 g_woh[FD*FD], g_wol[FD*FD];
__device__ __align__(16) __nv_bfloat16 g_qh[NBH*TT*DH], g_ql[NBH*TT*DH];
__device__ __align__(16) __nv_bfloat16 g_kh[NBH*TT*DH], g_kl[NBH*TT*DH];
__device__ __align__(16) float         g_vf[NBH*TT*DH];
__device__ __align__(16) __nv_bfloat16 g_vth[NBH*DH*TT], g_vtl[NBH*DH*TT];
__device__ __align__(16) __nv_bfloat16 g_oh[MROWS*FD], g_ol[MROWS*FD];

// ------------------------------ PTX helpers --------------------------------
__device__ __forceinline__ uint32_t smem_u32(const void* p) {
    uint32_t a;
    asm("{ .reg .u64 t; cvta.to.shared.u64 t, %1; cvt.u32.u64 %0, t; }" : "=r"(a) : "l"(p));
    return a;
}
#define CP16(dst, src) \
    asm volatile("cp.async.cg.shared.global [%0], [%1], 16;" :: "r"(dst), "l"(src) : "memory")
#define CP_COMMIT() asm volatile("cp.async.commit_group;" ::: "memory")
#define CP_WAIT0()  asm volatile("cp.async.wait_group 0;" ::: "memory")
#define CP_WAIT1()  asm volatile("cp.async.wait_group 1;" ::: "memory")
#define CP_WAIT2()  asm volatile("cp.async.wait_group 2;" ::: "memory")

#define LDSM4(r0,r1,r2,r3,addr) \
    asm volatile("ldmatrix.sync.aligned.m8n8.x4.shared.b16 {%0,%1,%2,%3}, [%4];" \
        : "=r"(r0), "=r"(r1), "=r"(r2), "=r"(r3) : "r"(addr))

#define MMA16816(d, a, b0v, b1v) \
    asm volatile("mma.sync.aligned.m16n8k16.row.col.f32.bf16.bf16.f32 " \
        "{%0,%1,%2,%3}, {%4,%5,%6,%7}, {%8,%9}, {%0,%1,%2,%3};" \
        : "+f"((d)[0]), "+f"((d)[1]), "+f"((d)[2]), "+f"((d)[3]) \
        : "r"((a)[0]), "r"((a)[1]), "r"((a)[2]), "r"((a)[3]), "r"(b0v), "r"(b1v))

#define SWZ(o) ((uint32_t)(o) ^ ((((uint32_t)(o)) >> 3) & 0x70))

__device__ __forceinline__ void split2(float v, __nv_bfloat16& h, __nv_bfloat16& l) {
    h = __float2bfloat16(v);
    l = __float2bfloat16(v - __bfloat162float(h));
}

// ------------- split-bf16 GEMM via mma.sync, 512 threads, 256x128 -----------
// C[m,n] = sum_k A[m,k]*B[n,k]; terms AhBh + AhBl + AlBh.
// 16 warps (4x4), warp tile 64x32, BK=32, 3-stage cp.async.
#define BM 256
#define BN 128
#define BK 32
#define ROWB 80
#define MAT_A (256*ROWB)              // 20480
#define MAT_B (128*ROWB)              // 10240
#define OFF_AH 0
#define OFF_AL MAT_A
#define OFF_BH (2*MAT_A)
#define OFF_BL (2*MAT_A + MAT_B)
#define STAGE_BYTES (2*MAT_A + 2*MAT_B)   // 61440
#define NSTAGE 3
#define SMEM_BYTES (NSTAGE*STAGE_BYTES)   // 184320

enum { EPI_QK = 0, EPI_VF = 1, EPI_OUT = 2 };

template<int EPI>
__global__ __launch_bounds__(512, 1) void gemm_mma(
    const __nv_bfloat16* __restrict__ Ah, const __nv_bfloat16* __restrict__ Al,
    const __nv_bfloat16* __restrict__ Bh, const __nv_bfloat16* __restrict__ Bl,
    const float* __restrict__ bias,
    float* __restrict__ outF, __nv_bfloat16* __restrict__ outH, __nv_bfloat16* __restrict__ outL,
    int K, float oscale)
{
    extern __shared__ char smem[];
    const uint32_t sb = smem_u32(smem);

    const int tid = threadIdx.x;
    const int wid = tid >> 5, lane = tid & 31;
    const int wm = wid >> 2, wn = wid & 3;     // 4 x 4 warps
    const int m0 = blockIdx.x * BM, n0 = blockIdx.y * BN;

    float acc[4][4][4] = {};

    // A: 2048 16B-chunks (hi) -> 2 per thread; B: 512 chunks -> 1 per thread
    const int ra0 = tid >> 2,          ca0 = tid & 3;
    const int ra1 = (tid + 512) >> 2,  ca1 = (tid + 512) & 3;
    const int rb  = tid >> 2,          cb  = tid & 3;

    auto load_stage = [&](int kb, int s) {
        const uint32_t st = sb + s * STAGE_BYTES;
        {
            size_t g = (size_t)(m0 + ra0) * K + kb * BK + ca0 * 8;
            uint32_t so = ra0 * ROWB + ca0 * 16;
            CP16(st + OFF_AH + so, Ah + g);
            CP16(st + OFF_AL + so, Al + g);
        }
        {
            size_t g = (size_t)(m0 + ra1) * K + kb * BK + ca1 * 8;
            uint32_t so = ra1 * ROWB + ca1 * 16;
            CP16(st + OFF_AH + so, Ah + g);
            CP16(st + OFF_AL + so, Al + g);
        }
        {
            size_t g = (size_t)(n0 + rb) * K + kb * BK + cb * 8;
            uint32_t so = rb * ROWB + cb * 16;
            CP16(st + OFF_BH + so, Bh + g);
            CP16(st + OFF_BL + so, Bl + g);
        }
    };

    const int NKB = K / BK;
    load_stage(0, 0); CP_COMMIT();
    if (NKB > 1) load_stage(1, 1);
    CP_COMMIT();

    const int a_row = wm * 64 + (lane & 7) + ((lane >> 3) & 1) * 8;
    const int a_kb  = ((lane >> 4) & 1) * 16;
    const int b_row = wn * 32 + (lane & 7) + (lane >= 16 ? 8 : 0);
    const int b_kb  = ((lane >> 3) & 1) * 16;

    for (int kb = 0; kb < NKB; kb++) {
        CP_WAIT1();
        __syncthreads();
        if (kb + 2 < NKB) load_stage(kb + 2, (kb + 2) % NSTAGE);
        CP_COMMIT();

        const uint32_t st = sb + (kb % NSTAGE) * STAGE_BYTES;
        #pragma unroll
        for (int ks = 0; ks < 2; ks++) {
            uint32_t bhf[2][4], blf[2][4];
            #pragma unroll
            for (int np = 0; np < 2; np++) {
                uint32_t bo = (b_row + np * 16) * ROWB + b_kb + ks * 32;
                LDSM4(bhf[np][0], bhf[np][1], bhf[np][2], bhf[np][3], st + OFF_BH + bo);
                LDSM4(blf[np][0], blf[np][1], blf[np][2], blf[np][3], st + OFF_BL + bo);
            }
            #pragma unroll
            for (int mf = 0; mf < 4; mf++) {
                uint32_t ah[4], al[4];
                uint32_t ao = (a_row + mf * 16) * ROWB + a_kb + ks * 32;
                LDSM4(ah[0], ah[1], ah[2], ah[3], st + OFF_AH + ao);
                LDSM4(al[0], al[1], al[2], al[3], st + OFF_AL + ao);
                #pragma unroll
                for (int nf = 0; nf < 4; nf++) {
                    const int np = nf >> 1, hi = (nf & 1) * 2;
                    MMA16816(acc[mf][nf], ah, bhf[np][hi], bhf[np][hi+1]);
                    MMA16816(acc[mf][nf], ah, blf[np][hi], blf[np][hi+1]);
                    MMA16816(acc[mf][nf], al, bhf[np][hi], bhf[np][hi+1]);
                }
            }
        }
        __syncthreads();
    }

    const int mrow = m0 + wm * 64 + (lane >> 2);
    const int ncol = n0 + wn * 32 + (lane & 3) * 2;

    #pragma unroll
    for (int mf = 0; mf < 4; mf++) {
        #pragma unroll
        for (int half = 0; half < 2; half++) {
            const int m = mrow + mf * 16 + half * 8;
            #pragma unroll
            for (int nf = 0; nf < 4; nf++) {
                const int n = ncol + nf * 8;
                float v0 = acc[mf][nf][half * 2];
                float v1 = acc[mf][nf][half * 2 + 1];

                if (EPI == EPI_QK) {
                    v0 = (v0 + __ldg(&bias[n])) * oscale;
                    v1 = (v1 + __ldg(&bias[n + 1])) * oscale;
                    const int t = m >> 3, b = m & 7, h = n >> 8, d = n & 255;
                    size_t o = ((size_t)(b * HH + h) * TT + t) * DH + d;
                    __nv_bfloat16 h0, l0, h1, l1; split2(v0, h0, l0); split2(v1, h1, l1);
                    __nv_bfloat162 ph; ph.x = h0; ph.y = h1;
                    __nv_bfloat162 pl; pl.x = l0; pl.y = l1;
                    *(__nv_bfloat162*)(outH + o) = ph;
                    *(__nv_bfloat162*)(outL + o) = pl;
                } else if (EPI == EPI_VF) {
                    v0 += __ldg(&bias[n]);  v1 += __ldg(&bias[n + 1]);
                    const int t = m >> 3, b = m & 7, h = n >> 8, d = n & 255;
                    size_t o = ((size_t)(b * HH + h) * TT + t) * DH + d;
                    float2 f; f.x = v0; f.y = v1;
                    *(float2*)(outF + o) = f;
                } else { // EPI_OUT
                    v0 += __ldg(&bias[n]);  v1 += __ldg(&bias[n + 1]);
                    size_t o = (size_t)m * FD + n;
                    float2 f; f.x = v0; f.y = v1;
                    *(float2*)(outF + o) = f;
                }
            }
        }
    }
}

// --------------------------- fused flash attention --------------------------
#define AMAT 8192
#define Q_OFF 0
#define KB_OFF 65536
#define V_OFF 98304
#define P_OFF 163840
#define RMAX_OFF 180224
#define RSUM_OFF 180736
#define ATT_SMEM 181248
#define NTILE (TT/64)   // 32

__global__ __launch_bounds__(256, 1) void attn_kernel()
{
    extern __shared__ char sm[];
    const uint32_t sb = smem_u32(sm);
    const int tid = threadIdx.x, lane = tid & 31, wid = tid >> 5;
    const int wm = wid & 3, wn = wid >> 2;             // 4 x 2 warp grid
    const int bh = blockIdx.y, m0 = blockIdx.x * 64;

    auto load_k = [&](int tile, int j, int buf) {
        const uint32_t dh = sb + KB_OFF + (buf * 2) * AMAT;
        const int n0 = tile * 64;
        #pragma unroll
        for (int i = 0; i < 2; i++) {
            int ci = tid + i * 256;
            int r = ci >> 3, c = ci & 7;
            size_t g = ((size_t)bh * TT + n0 + r) * DH + j * 64 + c * 8;
            uint32_t so = SWZ(r * 128 + c * 16);
            CP16(dh + so,        g_kh + g);
            CP16(dh + AMAT + so, g_kl + g);
        }
    };
    auto load_v = [&](int tile, int q) {
        const uint32_t dh = sb + V_OFF + (q * 2) * AMAT;
        const int n0 = tile * 64;
        #pragma unroll
        for (int i = 0; i < 2; i++) {
            int ci = tid + i * 256;
            int r = ci >> 3, c = ci & 7;
            size_t g = ((size_t)bh * DH + q * 64 + r) * TT + n0 + c * 8;
            uint32_t so = SWZ(r * 128 + c * 16);
            CP16(dh + so,        g_vth + g);
            CP16(dh + AMAT + so, g_vtl + g);
        }
    };

    #pragma unroll
    for (int i = 0; i < 16; i++) {
        int ci = tid + i * 256;
        int mat = ci >> 9, w = ci & 511, r = w >> 3, c = w & 7;
        int j = mat >> 1, hl = mat & 1;
        size_t g = ((size_t)bh * TT + m0 + r) * DH + j * 64 + c * 8;
        const __nv_bfloat16* src = hl ? g_ql : g_qh;
        CP16(sb + Q_OFF + mat * AMAT + SWZ(r * 128 + c * 16), src + g);
    }
    CP_COMMIT();
    load_k(0, 0, 0); CP_COMMIT();
    load_k(0, 1, 1); CP_COMMIT();
    load_v(0, 0); load_v(0, 1); CP_COMMIT();

    const int a_rl = (lane & 7) + ((lane >> 3) & 1) * 8;
    const int a_kb = ((lane >> 4) & 1) * 16;
    const int b_rl = (lane & 7) + (lane >= 16 ? 8 : 0);
    const int b_kb = ((lane >> 3) & 1) * 16;

    auto qk_chunk = [&](int j, int buf, float (*sacc)[4]) {
        const uint32_t qm = sb + Q_OFF + (j * 2) * AMAT;
        const uint32_t km = sb + KB_OFF + (buf * 2) * AMAT;
        #pragma unroll
        for (int ks = 0; ks < 4; ks++) {
            uint32_t qh[4], ql[4];
            uint32_t ao = SWZ((wm * 16 + a_rl) * 128 + a_kb + ks * 32);
            LDSM4(qh[0], qh[1], qh[2], qh[3], qm + ao);
            LDSM4(ql[0], ql[1], ql[2], ql[3], qm + AMAT + ao);
            #pragma unroll
            for (int g = 0; g < 2; g++) {
                uint32_t kh[4], kl[4];
                uint32_t bo = SWZ((wn * 32 + g * 16 + b_rl) * 128 + b_kb + ks * 32);
                LDSM4(kh[0], kh[1], kh[2], kh[3], km + bo);
                LDSM4(kl[0], kl[1], kl[2], kl[3], km + AMAT + bo);
                MMA16816(sacc[g*2],   qh, kh[0], kh[1]);
                MMA16816(sacc[g*2],   qh, kl[0], kl[1]);
                MMA16816(sacc[g*2],   ql, kh[0], kh[1]);
                MMA16816(sacc[g*2+1], qh, kh[2], kh[3]);
                MMA16816(sacc[g*2+1], qh, kl[2], kl[3]);
                MMA16816(sacc[g*2+1], ql, kh[2], kh[3]);
            }
        }
    };

    float oacc[16][4] = {};
    float mrun0 = -1e30f, mrun1 = -1e30f, lrun0 = 0.f, lrun1 = 0.f;
    const int r0 = wm * 16 + (lane >> 2), r1 = r0 + 8;
    float* rmax = (float*)(sm + RMAX_OFF);
    float* rsum = (float*)(sm + RSUM_OFF);

    for (int tile = 0; tile < NTILE; tile++) {
        float sacc[4][4] = {};

        CP_WAIT2(); __syncthreads();
        qk_chunk(0, 0, sacc);
        __syncthreads();
        load_k(tile, 2, 0); load_v(tile, 2); CP_COMMIT();

        CP_WAIT2(); __syncthreads();
        qk_chunk(1, 1, sacc);
        __syncthreads();
        load_k(tile, 3, 1); load_v(tile, 3); CP_COMMIT();

        CP_WAIT1(); __syncthreads();
        qk_chunk(2, 0, sacc);
        __syncthreads();
        if (tile + 1 < NTILE) load_k(tile + 1, 0, 0);
        CP_COMMIT();

        CP_WAIT1(); __syncthreads();
        qk_chunk(3, 1, sacc);
        __syncthreads();
        if (tile + 1 < NTILE) load_k(tile + 1, 1, 1);
        CP_COMMIT();

        float mx0 = -1e30f, mx1 = -1e30f;
        #pragma unroll
        for (int nf = 0; nf < 4; nf++) {
            mx0 = fmaxf(mx0, fmaxf(sacc[nf][0], sacc[nf][1]));
            mx1 = fmaxf(mx1, fmaxf(sacc[nf][2], sacc[nf][3]));
        }
        mx0 = fmaxf(mx0, __shfl_xor_sync(0xffffffffu, mx0, 1));
        mx0 = fmaxf(mx0, __shfl_xor_sync(0xffffffffu, mx0, 2));
        mx1 = fmaxf(mx1, __shfl_xor_sync(0xffffffffu, mx1, 1));
        mx1 = fmaxf(mx1, __shfl_xor_sync(0xffffffffu, mx1, 2));
        if ((lane & 3) == 0) { rmax[wn * 64 + r0] = mx0; rmax[wn * 64 + r1] = mx1; }
        __syncthreads();

        float mn0 = fmaxf(mrun0, fmaxf(rmax[r0], rmax[64 + r0]));
        float mn1 = fmaxf(mrun1, fmaxf(rmax[r1], rmax[64 + r1]));
        float a0 = __expf(mrun0 - mn0), a1 = __expf(mrun1 - mn1);
        mrun0 = mn0; mrun1 = mn1;

        float s0 = 0.f, s1 = 0.f;
        #pragma unroll
        for (int nf = 0; nf < 4; nf++) {
            sacc[nf][0] = __expf(sacc[nf][0] - mn0);
            sacc[nf][1] = __expf(sacc[nf][1] - mn0);
            sacc[nf][2] = __expf(sacc[nf][2] - mn1);
            sacc[nf][3] = __expf(sacc[nf][3] - mn1);
            s0 += sacc[nf][0] + sacc[nf][1];
            s1 += sacc[nf][2] + sacc[nf][3];
        }
        s0 += __shfl_xor_sync(0xffffffffu, s0, 1);
        s0 += __shfl_xor_sync(0xffffffffu, s0, 2);
        s1 += __shfl_xor_sync(0xffffffffu, s1, 1);
        s1 += __shfl_xor_sync(0xffffffffu, s1, 2);
        if ((lane & 3) == 0) { rsum[wn * 64 + r0] = s0; rsum[wn * 64 + r1] = s1; }

        #pragma unroll
        for (int nf = 0; nf < 16; nf++) {
            oacc[nf][0] *= a0; oacc[nf][1] *= a0;
            oacc[nf][2] *= a1; oacc[nf][3] *= a1;
        }

        #pragma unroll
        for (int nf = 0; nf < 4; nf++) {
            int c = wn * 32 + nf * 8 + (lane & 3) * 2;
            __nv_bfloat16 h0, l0, h1, l1;
            split2(sacc[nf][0], h0, l0); split2(sacc[nf][1], h1, l1);
            __nv_bfloat162 ph; ph.x = h0; ph.y = h1;
            __nv_bfloat162 pl; pl.x = l0; pl.y = l1;
            uint32_t off = SWZ(r0 * 128 + c * 2);
            *(__nv_bfloat162*)(sm + P_OFF + off) = ph;
            *(__nv_bfloat162*)(sm + P_OFF + AMAT + off) = pl;
            split2(sacc[nf][2], h0, l0); split2(sacc[nf][3], h1, l1);
            ph.x = h0; ph.y = h1; pl.x = l0; pl.y = l1;
            off = SWZ(r1 * 128 + c * 2);
            *(__nv_bfloat162*)(sm + P_OFF + off) = ph;
            *(__nv_bfloat162*)(sm + P_OFF + AMAT + off) = pl;
        }
        __syncthreads();

        lrun0 = lrun0 * a0 + rsum[r0] + rsum[64 + r0];
        lrun1 = lrun1 * a1 + rsum[r1] + rsum[64 + r1];

        {
            const uint32_t pm = sb + P_OFF;
            #pragma unroll
            for (int ks = 0; ks < 4; ks++) {
                uint32_t ph[4], pl[4];
                uint32_t ao = SWZ((wm * 16 + a_rl) * 128 + a_kb + ks * 32);
                LDSM4(ph[0], ph[1], ph[2], ph[3], pm + ao);
                LDSM4(pl[0], pl[1], pl[2], pl[3], pm + AMAT + ao);
                #pragma unroll
                for (int g = 0; g < 8; g++) {
                    const int q = wn * 2 + (g >> 2), dr = (g & 3) * 16;
                    const uint32_t vm = sb + V_OFF + (q * 2) * AMAT;
                    uint32_t bo = SWZ((dr + b_rl) * 128 + b_kb + ks * 32);
                    uint32_t vh[4], vl[4];
                    LDSM4(vh[0], vh[1], vh[2], vh[3], vm + bo);
                    LDSM4(vl[0], vl[1], vl[2], vl[3], vm + AMAT + bo);
                    MMA16816(oacc[g*2],   ph, vh[0], vh[1]);
                    MMA16816(oacc[g*2],   ph, vl[0], vl[1]);
                    MMA16816(oacc[g*2],   pl, vh[0], vh[1]);
                    MMA16816(oacc[g*2+1], ph, vh[2], vh[3]);
                    MMA16816(oacc[g*2+1], ph, vl[2], vl[3]);
                    MMA16816(oacc[g*2+1], pl, vh[2], vh[3]);
                }
            }
        }
        __syncthreads();
        if (tile + 1 < NTILE) { load_v(tile + 1, 0); load_v(tile + 1, 1); }
        CP_COMMIT();
    }

    const int bb = bh / HH, hh = bh % HH;
    const float inv0 = 1.f / lrun0, inv1 = 1.f / lrun1;
    #pragma unroll
    for (int nf = 0; nf < 16; nf++) {
        int d = wn * 128 + nf * 8 + (lane & 3) * 2;
        {
            int t = m0 + r0;
            float v0 = oacc[nf][0] * inv0, v1 = oacc[nf][1] * inv0;
            size_t o = ((size_t)t * BB + bb) * FD + hh * DH + d;
            __nv_bfloat16 h0, l0, h1, l1; split2(v0, h0, l0); split2(v1, h1, l1);
            __nv_bfloat162 ph; ph.x = h0; ph.y = h1;
            __nv_bfloat162 pl; pl.x = l0; pl.y = l1;
            *(__nv_bfloat162*)(g_oh + o) = ph;
            *(__nv_bfloat162*)(g_ol + o) = pl;
        }
        {
            int t = m0 + r1;
            float v0 = oacc[nf][2] * inv1, v1 = oacc[nf][3] * inv1;
            size_t o = ((size_t)t * BB + bb) * FD + hh * DH + d;
            __nv_bfloat16 h0, l0, h1, l1; split2(v0, h0, l0); split2(v1, h1, l1);
            __nv_bfloat162 ph; ph.x = h0; ph.y = h1;
            __nv_bfloat162 pl; pl.x = l0; pl.y = l1;
            *(__nv_bfloat162*)(g_oh + o) = ph;
            *(__nv_bfloat162*)(g_ol + o) = pl;
        }
    }
}

// ------------------------------ helper kernels ------------------------------
__global__ __launch_bounds__(256) void split_kernel(
    const float* __restrict__ in, __nv_bfloat16* __restrict__ h,
    __nv_bfloat16* __restrict__ l, int n4)
{
    int i = blockIdx.x * 256 + threadIdx.x;
    if (i >= n4) return;
    float4 v = *(const float4*)(in + (size_t)i * 4);
    __nv_bfloat16 h0,l0,h1,l1,h2,l2,h3,l3;
    split2(v.x,h0,l0); split2(v.y,h1,l1); split2(v.z,h2,l2); split2(v.w,h3,l3);
    __nv_bfloat162 a; a.x=h0; a.y=h1; __nv_bfloat162 b; b.x=h2; b.y=h3;
    __nv_bfloat162 c; c.x=l0; c.y=l1; __nv_bfloat162 d; d.x=l2; d.y=l3;
    *(__nv_bfloat162*)(h + (size_t)i*4)     = a;
    *(__nv_bfloat162*)(h + (size_t)i*4 + 2) = b;
    *(__nv_bfloat162*)(l + (size_t)i*4)     = c;
    *(__nv_bfloat162*)(l + (size_t)i*4 + 2) = d;
}

// all 4 weight matrices in one launch; blockIdx.y selects which
__global__ __launch_bounds__(256) void split_w_kernel(
    const float* __restrict__ w0, const float* __restrict__ w1,
    const float* __restrict__ w2, const float* __restrict__ w3,
    __nv_bfloat16* __restrict__ h0o, __nv_bfloat16* __restrict__ l0o,
    __nv_bfloat16* __restrict__ h1o, __nv_bfloat16* __restrict__ l1o,
    __nv_bfloat16* __restrict__ h2o, __nv_bfloat16* __restrict__ l2o,
    __nv_bfloat16* __restrict__ h3o, __nv_bfloat16* __restrict__ l3o)
{
    const int which = blockIdx.y;
    const float* in = which == 0 ? w0 : which == 1 ? w1 : which == 2 ? w2 : w3;
    __nv_bfloat16* h = which == 0 ? h0o : which == 1 ? h1o : which == 2 ? h2o : h3o;
    __nv_bfloat16* l = which == 0 ? l0o : which == 1 ? l1o : which == 2 ? l2o : l3o;
    int i = blockIdx.x * 256 + threadIdx.x;
    if (i >= FD*FD/4) return;
    float4 v = *(const float4*)(in + (size_t)i * 4);
    __nv_bfloat16 a0,b0,a1,b1,a2,b2,a3,b3;
    split2(v.x,a0,b0); split2(v.y,a1,b1); split2(v.z,a2,b2); split2(v.w,a3,b3);
    __nv_bfloat162 p; p.x=a0; p.y=a1; __nv_bfloat162 q; q.x=a2; q.y=a3;
    __nv_bfloat162 r; r.x=b0; r.y=b1; __nv_bfloat162 s; s.x=b2; s.y=b3;
    *(__nv_bfloat162*)(h + (size_t)i*4)     = p;
    *(__nv_bfloat162*)(h + (size_t)i*4 + 2) = q;
    *(__nv_bfloat162*)(l + (size_t)i*4)     = r;
    *(__nv_bfloat162*)(l + (size_t)i*4 + 2) = s;
}

// V (BH,T,D) fp32 -> Vt hi/lo (BH,D,T) bf16
__global__ __launch_bounds__(256) void vtrans_kernel()
{
    __shared__ float tl[32][33];
    const int bh = blockIdx.z;
    const int d0 = blockIdx.x * 32, t0 = blockIdx.y * 32;
    const int tx = threadIdx.x & 31, ty = threadIdx.x >> 5;
    const float* src = g_vf + ((size_t)bh * TT + t0) * DH + d0;
    #pragma unroll
    for (int i = 0; i < 4; i++)
        tl[ty + 8*i][tx] = src[(size_t)(ty + 8*i) * DH + tx];
    __syncthreads();
    #pragma unroll
    for (int i = 0; i < 4; i++) {
        int d = ty + 8*i;
        float v = tl[tx][d];
        __nv_bfloat16 h, l; split2(v, h, l);
        size_t o = ((size_t)bh * DH + d0 + d) * TT + t0 + tx;
        g_vth[o] = h; g_vtl[o] = l;
    }
}

// --------------------------------- launch ----------------------------------
extern "C" void kernel_launch(void* const* d_in, const int* in_sizes, int n_in,
                              void* d_out, int out_size)
{
    const float* x  = (const float*)d_in[0];
    const float* Wq = (const float*)d_in[1];
    const float* bq = (const float*)d_in[2];
    const float* Wk = (const float*)d_in[3];
    const float* bk = (const float*)d_in[4];
    const float* Wv = (const float*)d_in[5];
    const float* bv = (const float*)d_in[6];
    const float* Wo = (const float*)d_in[7];
    const float* bo = (const float*)d_in[8];
    float* out = (float*)d_out;

    cudaFuncSetAttribute(gemm_mma<EPI_QK>,  cudaFuncAttributeMaxDynamicSharedMemorySize, SMEM_BYTES);
    cudaFuncSetAttribute(gemm_mma<EPI_VF>,  cudaFuncAttributeMaxDynamicSharedMemorySize, SMEM_BYTES);
    cudaFuncSetAttribute(gemm_mma<EPI_OUT>, cudaFuncAttributeMaxDynamicSharedMemorySize, SMEM_BYTES);
    cudaFuncSetAttribute(attn_kernel,       cudaFuncAttributeMaxDynamicSharedMemorySize, ATT_SMEM);

    __nv_bfloat16 *xh,*xl,*wqh,*wql,*wkh,*wkl,*wvh,*wvl,*woh,*wol;
    __nv_bfloat16 *qh,*ql,*kh,*kl,*oh,*ol;
    float *vf;
    cudaGetSymbolAddress((void**)&xh, g_xh);  cudaGetSymbolAddress((void**)&xl, g_xl);
    cudaGetSymbolAddress((void**)&wqh, g_wqh); cudaGetSymbolAddress((void**)&wql, g_wql);
    cudaGetSymbolAddress((void**)&wkh, g_wkh); cudaGetSymbolAddress((void**)&wkl, g_wkl);
    cudaGetSymbolAddress((void**)&wvh, g_wvh); cudaGetSymbolAddress((void**)&wvl, g_wvl);
    cudaGetSymbolAddress((void**)&woh, g_woh); cudaGetSymbolAddress((void**)&wol, g_wol);
    cudaGetSymbolAddress((void**)&qh, g_qh);  cudaGetSymbolAddress((void**)&ql, g_ql);
    cudaGetSymbolAddress((void**)&kh, g_kh);  cudaGetSymbolAddress((void**)&kl, g_kl);
    cudaGetSymbolAddress((void**)&vf, g_vf);
    cudaGetSymbolAddress((void**)&oh, g_oh);  cudaGetSymbolAddress((void**)&ol, g_ol);

    // launch 0: x split
    split_kernel<<<(MROWS*FD/4 + 255)/256, 256>>>(x, xh, xl, MROWS*FD/4);
    // launch 1: all W splits
    dim3 gW((FD*FD/4 + 255)/256, 4);
    split_w_kernel<<<gW, 256>>>(Wq, Wk, Wv, Wo, wqh, wql, wkh, wkl, wvh, wvl, woh, wol);

    dim3 gP(MROWS/BM, FD/BN);   // 64 x 6
    // launch 2: V projection
    gemm_mma<EPI_VF><<<gP, 512, SMEM_BYTES>>>(xh, xl, wvh, wvl, bv, vf, nullptr, nullptr, FD, 1.0f);
    // launch 3: V transpose + split
    dim3 gT(DH/32, TT/32, NBH);
    vtrans_kernel<<<gT, 256>>>();
    // launch 4: K projection
    gemm_mma<EPI_QK><<<gP, 512, SMEM_BYTES>>>(xh, xl, wkh, wkl, bk, nullptr, kh, kl, FD, 1.0f);
    // launch 5: Q projection (profiler target at -s 5)
    gemm_mma<EPI_QK><<<gP, 512, SMEM_BYTES>>>(xh, xl, wqh, wql, bq, nullptr, qh, ql, FD, 0.125f);
    // launch 6: fused attention
    dim3 gA(TT/64, NBH);
    attn_kernel<<<gA, 256, ATT_SMEM>>>();
    // launch 7: output projection
    gemm_mma<EPI_OUT><<<gP, 512, SMEM_BYTES>>>(oh, ol, woh, wol, bo, out, nullptr, nullptr, FD, 1.0f);
}